// round 10
// baseline (speedup 1.0000x reference)
#include <cuda_runtime.h>
#include <cstdint>

#define BATCH  4096
#define TSTEPS 100
#define DDIM   100
#define OOUT   3
#define CW     (BATCH * OOUT)

#define FPSCALE 67108864.0f                       /* 2^26 */
#define INV_FPSCALE 1.490116119384765625e-8f      /* 2^-26 */

#define ROWB    400                /* bytes per 100-float row */
#define PAIRB   1600               /* x,u rows for 2 timesteps */
#define RP      3                  /* ring depth in row-pairs  */
#define NPAIRS  (TSTEPS / 2)       /* 50 */

__device__ __forceinline__ void cp16(unsigned int dst_smem, const void* src) {
    asm volatile("cp.async.cg.shared.global [%0], [%1], 16;\n"
                 :: "r"(dst_smem), "l"(src));
}
__device__ __forceinline__ void cp_commit() {
    asm volatile("cp.async.commit_group;\n");
}
__device__ __forceinline__ void cp_wait2() {
    asm volatile("cp.async.wait_group 2;\n");
}

// One warp per batch element. cp.async ring of 3 row-pairs per warp in smem
// (6 rows / 4.8KB in flight) -> 4-bit mask -> smem LUT of fixed-point subset
// sums -> REDUX.SUM per channel -> per-lane-channel leaky scan.
__global__ __launch_bounds__(128, 8) void leaky_fused(
    const float* __restrict__ x, const float* __restrict__ u,
    const float* __restrict__ W, const float* __restrict__ bias,
    const float* __restrict__ betap, const float* __restrict__ thrp,
    float* __restrict__ out)
{
    __shared__ int4 lut[16 * 32];                       // 2 KB
    __shared__ __align__(16) char ring[4][RP * PAIRB];  // 19.2 KB

    // LUT[mask][lane] = fixed-point subset sums of this lane's 4 weights
    for (int e = threadIdx.x; e < 16 * 32; e += 128) {
        const int mask = e >> 5;
        const int ln   = e & 31;
        int s0 = 0, s1 = 0, s2 = 0;
        if (ln < (DDIM / 4)) {
            #pragma unroll
            for (int bit = 0; bit < 4; ++bit) {
                if ((mask >> bit) & 1) {
                    const int col = ln * 4 + bit;
                    s0 += __float2int_rn(__ldg(W + 0 * DDIM + col) * FPSCALE);
                    s1 += __float2int_rn(__ldg(W + 1 * DDIM + col) * FPSCALE);
                    s2 += __float2int_rn(__ldg(W + 2 * DDIM + col) * FPSCALE);
                }
            }
        }
        lut[(mask << 5) | ln] = make_int4(s0, s1, s2, 0);
    }
    __syncthreads();

    const int wid  = threadIdx.x >> 5;
    const int gw   = (blockIdx.x << 2) | wid;   // batch id
    const int lane = threadIdx.x & 31;
    const bool act = (lane < (DDIM / 4));       // 25 active lanes

    const float beta = __ldg(betap);
    const float thr  = __ldg(thrp);
    const float bl   = __ldg(bias + ((lane < 2) ? lane : 2));

    const char* __restrict__ xb = (const char*)(x + (size_t)gw * (TSTEPS * DDIM));
    const char* __restrict__ ub = (const char*)(u + (size_t)gw * (TSTEPS * DDIM));

    const unsigned int rbase = (unsigned int)__cvta_generic_to_shared(ring[wid]);
    const int loff = lane * 16;

    // prologue: issue pairs 0..RP-1
    #pragma unroll
    for (int p = 0; p < RP; ++p) {
        if (act) {
            const unsigned int s = rbase + p * PAIRB + loff;
            cp16(s,               xb + (2 * p + 0) * ROWB + loff);
            cp16(s + ROWB,        ub + (2 * p + 0) * ROWB + loff);
            cp16(s + 2 * ROWB,    xb + (2 * p + 1) * ROWB + loff);
            cp16(s + 3 * ROWB,    ub + (2 * p + 1) * ROWB + loff);
        }
        cp_commit();
    }

    float* __restrict__ spk = out;
    float* __restrict__ mem = out + (size_t)TSTEPS * CW;

    float m = 0.f;   // this lane's channel membrane
    float r = 0.f;   // reset carried from previous spike

    int slot = 0;
    for (int p = 0; p < NPAIRS; ++p) {
        cp_wait2();   // FIFO groups: pair p is now complete

        int ma = 0, mb = 0;
        if (act) {
            const char* base = ring[wid] + slot * PAIRB + loff;
            const float4 xa  = *(const float4*)(base);
            const float4 ua  = *(const float4*)(base + ROWB);
            const float4 xbv = *(const float4*)(base + 2 * ROWB);
            const float4 ubv = *(const float4*)(base + 3 * ROWB);
            ma = (ua.x < xa.x) | ((ua.y < xa.y) << 1)
               | ((ua.z < xa.z) << 2) | ((ua.w < xa.w) << 3);
            mb = (ubv.x < xbv.x) | ((ubv.y < xbv.y) << 1)
               | ((ubv.z < xbv.z) << 2) | ((ubv.w < xbv.w) << 3);
        }

        // refill this slot with pair p+RP while we compute
        if (act && (p + RP < NPAIRS)) {
            const unsigned int s = rbase + slot * PAIRB + loff;
            const int row = 2 * (p + RP);
            cp16(s,            xb + (row + 0) * ROWB + loff);
            cp16(s + ROWB,     ub + (row + 0) * ROWB + loff);
            cp16(s + 2 * ROWB, xb + (row + 1) * ROWB + loff);
            cp16(s + 3 * ROWB, ub + (row + 1) * ROWB + loff);
        }
        cp_commit();   // always: keeps group indices aligned with pair ids

        const int4 la = lut[(ma << 5) | lane];
        const int4 lb = lut[(mb << 5) | lane];

        const int sa0 = __reduce_add_sync(0xffffffffu, la.x);
        const int sb0 = __reduce_add_sync(0xffffffffu, lb.x);
        const int sa1 = __reduce_add_sync(0xffffffffu, la.y);
        const int sb1 = __reduce_add_sync(0xffffffffu, lb.y);
        const int sa2 = __reduce_add_sync(0xffffffffu, la.z);
        const int sb2 = __reduce_add_sync(0xffffffffu, lb.z);

        const int ia = (lane == 0) ? sa0 : ((lane == 1) ? sa1 : sa2);
        const int ib = (lane == 0) ? sb0 : ((lane == 1) ? sb1 : sb2);
        const float pa = (float)ia * INV_FPSCALE;
        const float pb = (float)ib * INV_FPSCALE;

        const int t = 2 * p;
        // step t
        m = beta * m + (pa + bl) - r;
        float sp = (m - thr > 0.f) ? 1.f : 0.f;
        r = sp * thr;
        if (lane < OOUT) {
            const size_t o = (size_t)t * CW + (size_t)gw * OOUT + lane;
            __stcs(spk + o, sp);
            __stcs(mem + o, m);
        }
        // step t+1
        m = beta * m + (pb + bl) - r;
        sp = (m - thr > 0.f) ? 1.f : 0.f;
        r = sp * thr;
        if (lane < OOUT) {
            const size_t o = (size_t)(t + 1) * CW + (size_t)gw * OOUT + lane;
            __stcs(spk + o, sp);
            __stcs(mem + o, m);
        }

        slot = (slot + 1 == RP) ? 0 : slot + 1;
    }
}

extern "C" void kernel_launch(void* const* d_in, const int* in_sizes, int n_in,
                              void* d_out, int out_size)
{
    const float* x    = (const float*)d_in[0];
    const float* u    = (const float*)d_in[1];
    const float* W    = (const float*)d_in[2];
    const float* bias = (const float*)d_in[3];
    const float* beta = (const float*)d_in[4];
    const float* thr  = (const float*)d_in[5];
    float* out = (float*)d_out;

    leaky_fused<<<BATCH / 4, 128>>>(x, u, W, bias, beta, thr, out);
}

// round 11
// speedup vs baseline: 1.0502x; 1.0502x over previous
#include <cuda_runtime.h>

#define BATCH  4096
#define TSTEPS 100
#define DDIM   100
#define OOUT   3
#define CW     (BATCH * OOUT)

#define FPSCALE 67108864.0f                       /* 2^26 */
#define INV_FPSCALE 1.490116119384765625e-8f      /* 2^-26 */

// One warp per batch element, 4 timesteps per loop iteration (2 pipelined
// register row-pairs). 4-bit spike mask -> smem LUT of fixed-point subset
// sums -> REDUX.SUM per channel -> per-lane-channel leaky scan.
// Outputs staged in smem, written coalesced (48B/t per block) at the end.
__global__ __launch_bounds__(128, 8) void leaky_fused(
    const float* __restrict__ x, const float* __restrict__ u,
    const float* __restrict__ W, const float* __restrict__ bias,
    const float* __restrict__ betap, const float* __restrict__ thrp,
    float* __restrict__ out)
{
    __shared__ int4  lut[16 * 32];            // 2 KB
    __shared__ float stg_spk[TSTEPS * 12];    // 4.8 KB  [t][wid*3+chan]
    __shared__ float stg_mem[TSTEPS * 12];    // 4.8 KB

    // LUT[mask][lane] = fixed-point subset sums of this lane's 4 weights
    for (int e = threadIdx.x; e < 16 * 32; e += 128) {
        const int mask = e >> 5;
        const int ln   = e & 31;
        int s0 = 0, s1 = 0, s2 = 0;
        if (ln < (DDIM / 4)) {
            #pragma unroll
            for (int bit = 0; bit < 4; ++bit) {
                if ((mask >> bit) & 1) {
                    const int col = ln * 4 + bit;
                    s0 += __float2int_rn(__ldg(W + 0 * DDIM + col) * FPSCALE);
                    s1 += __float2int_rn(__ldg(W + 1 * DDIM + col) * FPSCALE);
                    s2 += __float2int_rn(__ldg(W + 2 * DDIM + col) * FPSCALE);
                }
            }
        }
        lut[(mask << 5) | ln] = make_int4(s0, s1, s2, 0);
    }
    __syncthreads();

    const int wid  = threadIdx.x >> 5;
    const int gw   = (blockIdx.x << 2) | wid;   // batch id
    const int lane = threadIdx.x & 31;
    const bool act = (lane < (DDIM / 4));       // 25 active load lanes

    const float beta = __ldg(betap);
    const float thr  = __ldg(thrp);
    const float bl   = __ldg(bias + ((lane < 2) ? lane : 2));

    const float4 z = make_float4(0.f, 0.f, 0.f, 0.f);
    const float4* __restrict__ xr = (const float4*)(x + (size_t)gw * (TSTEPS * DDIM));
    const float4* __restrict__ ur = (const float4*)(u + (size_t)gw * (TSTEPS * DDIM));

    // two row-pairs in flight: P = rows (t, t+1), Q = rows (t+2, t+3)
    float4 xp0 = z, up0 = z, xp1 = z, up1 = z;
    float4 xq0 = z, uq0 = z, xq1 = z, uq1 = z;
    if (act) {
        xp0 = __ldcs(xr + 0 * (DDIM / 4) + lane);  up0 = __ldcs(ur + 0 * (DDIM / 4) + lane);
        xp1 = __ldcs(xr + 1 * (DDIM / 4) + lane);  up1 = __ldcs(ur + 1 * (DDIM / 4) + lane);
        xq0 = __ldcs(xr + 2 * (DDIM / 4) + lane);  uq0 = __ldcs(ur + 2 * (DDIM / 4) + lane);
        xq1 = __ldcs(xr + 3 * (DDIM / 4) + lane);  uq1 = __ldcs(ur + 3 * (DDIM / 4) + lane);
    }

    const int sbase = wid * 3 + lane;   // staging column for lane<3
    float m = 0.f;                      // this lane's channel membrane
    float r = 0.f;                      // reset carried from previous spike

    for (int t = 0; t < TSTEPS; t += 4) {
        // ---------------- stage 1: rows t, t+1 (pair P) ----------------
        {
            const int ma = (up0.x < xp0.x) | ((up0.y < xp0.y) << 1)
                         | ((up0.z < xp0.z) << 2) | ((up0.w < xp0.w) << 3);
            const int mb = (up1.x < xp1.x) | ((up1.y < xp1.y) << 1)
                         | ((up1.z < xp1.z) << 2) | ((up1.w < xp1.w) << 3);

            if (act && (t + 4 < TSTEPS)) {      // refill P with rows t+4, t+5
                const int base = (t + 4) * (DDIM / 4) + lane;
                xp0 = __ldcs(xr + base);              up0 = __ldcs(ur + base);
                xp1 = __ldcs(xr + base + (DDIM / 4)); up1 = __ldcs(ur + base + (DDIM / 4));
            }

            const int4 la = lut[(ma << 5) | lane];
            const int4 lb = lut[(mb << 5) | lane];
            const int sa0 = __reduce_add_sync(0xffffffffu, la.x);
            const int sb0 = __reduce_add_sync(0xffffffffu, lb.x);
            const int sa1 = __reduce_add_sync(0xffffffffu, la.y);
            const int sb1 = __reduce_add_sync(0xffffffffu, lb.y);
            const int sa2 = __reduce_add_sync(0xffffffffu, la.z);
            const int sb2 = __reduce_add_sync(0xffffffffu, lb.z);

            const int ia = (lane == 0) ? sa0 : ((lane == 1) ? sa1 : sa2);
            const int ib = (lane == 0) ? sb0 : ((lane == 1) ? sb1 : sb2);
            const float pa = (float)ia * INV_FPSCALE;
            const float pb = (float)ib * INV_FPSCALE;

            m = beta * m + (pa + bl) - r;
            float sp = (m - thr > 0.f) ? 1.f : 0.f;
            r = sp * thr;
            if (lane < OOUT) { stg_spk[t * 12 + sbase] = sp; stg_mem[t * 12 + sbase] = m; }

            m = beta * m + (pb + bl) - r;
            sp = (m - thr > 0.f) ? 1.f : 0.f;
            r = sp * thr;
            if (lane < OOUT) { stg_spk[(t + 1) * 12 + sbase] = sp; stg_mem[(t + 1) * 12 + sbase] = m; }
        }
        // ---------------- stage 2: rows t+2, t+3 (pair Q) ----------------
        {
            const int ma = (uq0.x < xq0.x) | ((uq0.y < xq0.y) << 1)
                         | ((uq0.z < xq0.z) << 2) | ((uq0.w < xq0.w) << 3);
            const int mb = (uq1.x < xq1.x) | ((uq1.y < xq1.y) << 1)
                         | ((uq1.z < xq1.z) << 2) | ((uq1.w < xq1.w) << 3);

            if (act && (t + 6 < TSTEPS)) {      // refill Q with rows t+6, t+7
                const int base = (t + 6) * (DDIM / 4) + lane;
                xq0 = __ldcs(xr + base);              uq0 = __ldcs(ur + base);
                xq1 = __ldcs(xr + base + (DDIM / 4)); uq1 = __ldcs(ur + base + (DDIM / 4));
            }

            const int4 la = lut[(ma << 5) | lane];
            const int4 lb = lut[(mb << 5) | lane];
            const int sa0 = __reduce_add_sync(0xffffffffu, la.x);
            const int sb0 = __reduce_add_sync(0xffffffffu, lb.x);
            const int sa1 = __reduce_add_sync(0xffffffffu, la.y);
            const int sb1 = __reduce_add_sync(0xffffffffu, lb.y);
            const int sa2 = __reduce_add_sync(0xffffffffu, la.z);
            const int sb2 = __reduce_add_sync(0xffffffffu, lb.z);

            const int ia = (lane == 0) ? sa0 : ((lane == 1) ? sa1 : sa2);
            const int ib = (lane == 0) ? sb0 : ((lane == 1) ? sb1 : sb2);
            const float pa = (float)ia * INV_FPSCALE;
            const float pb = (float)ib * INV_FPSCALE;

            m = beta * m + (pa + bl) - r;
            float sp = (m - thr > 0.f) ? 1.f : 0.f;
            r = sp * thr;
            if (lane < OOUT) { stg_spk[(t + 2) * 12 + sbase] = sp; stg_mem[(t + 2) * 12 + sbase] = m; }

            m = beta * m + (pb + bl) - r;
            sp = (m - thr > 0.f) ? 1.f : 0.f;
            r = sp * thr;
            if (lane < OOUT) { stg_spk[(t + 3) * 12 + sbase] = sp; stg_mem[(t + 3) * 12 + sbase] = m; }
        }
    }

    // ---------------- coalesced writeout: 48B contiguous per t per block ----
    __syncthreads();
    float* __restrict__ spk = out;
    float* __restrict__ mem = out + (size_t)TSTEPS * CW;
    const size_t obase = (size_t)(blockIdx.x << 2) * OOUT;   // gw0 * 3
    for (int idx = threadIdx.x; idx < TSTEPS * 12; idx += 128) {
        const int t = idx / 12;
        const int c = idx - t * 12;
        const size_t o = (size_t)t * CW + obase + c;
        __stcs(spk + o, stg_spk[idx]);
        __stcs(mem + o, stg_mem[idx]);
    }
}

extern "C" void kernel_launch(void* const* d_in, const int* in_sizes, int n_in,
                              void* d_out, int out_size)
{
    const float* x    = (const float*)d_in[0];
    const float* u    = (const float*)d_in[1];
    const float* W    = (const float*)d_in[2];
    const float* bias = (const float*)d_in[3];
    const float* beta = (const float*)d_in[4];
    const float* thr  = (const float*)d_in[5];
    float* out = (float*)d_out;

    leaky_fused<<<BATCH / 4, 128>>>(x, u, W, bias, beta, thr, out);
}

// round 12
// speedup vs baseline: 1.1033x; 1.0506x over previous
#include <cuda_runtime.h>

#define BATCH  4096
#define TSTEPS 100
#define DDIM   100
#define OOUT   3
#define CW     (BATCH * OOUT)

#define FPSCALE 67108864.0f                       /* 2^26 */
#define INV_FPSCALE 1.490116119384765625e-8f      /* 2^-26 */

// One warp per batch element, 4 timesteps per loop iteration (2 pipelined
// register row-pairs). 4-bit spike mask -> smem LUT of fixed-point subset
// sums -> REDUX.SUM per channel -> per-lane-channel leaky scan.
// R12: default-policy loads (no .cs) so row-junction cache lines survive
// between the two adjacent-row LDGs that share them.
__global__ __launch_bounds__(128, 8) void leaky_fused(
    const float* __restrict__ x, const float* __restrict__ u,
    const float* __restrict__ W, const float* __restrict__ bias,
    const float* __restrict__ betap, const float* __restrict__ thrp,
    float* __restrict__ out)
{
    __shared__ int4 lut[16 * 32];   // LUT[mask][lane] = fixed-point subset sums

    for (int e = threadIdx.x; e < 16 * 32; e += 128) {
        const int mask = e >> 5;
        const int ln   = e & 31;
        int s0 = 0, s1 = 0, s2 = 0;
        if (ln < (DDIM / 4)) {
            #pragma unroll
            for (int bit = 0; bit < 4; ++bit) {
                if ((mask >> bit) & 1) {
                    const int col = ln * 4 + bit;
                    s0 += __float2int_rn(__ldg(W + 0 * DDIM + col) * FPSCALE);
                    s1 += __float2int_rn(__ldg(W + 1 * DDIM + col) * FPSCALE);
                    s2 += __float2int_rn(__ldg(W + 2 * DDIM + col) * FPSCALE);
                }
            }
        }
        lut[(mask << 5) | ln] = make_int4(s0, s1, s2, 0);
    }
    __syncthreads();

    const int gw   = (blockIdx.x << 2) | (threadIdx.x >> 5);  // batch id
    const int lane = threadIdx.x & 31;
    const bool act = (lane < (DDIM / 4));   // 25 active load lanes

    const float beta = __ldg(betap);
    const float thr  = __ldg(thrp);
    const float bl   = __ldg(bias + ((lane < 2) ? lane : 2));

    const float4 z = make_float4(0.f, 0.f, 0.f, 0.f);
    const float4* __restrict__ xr = (const float4*)(x + (size_t)gw * (TSTEPS * DDIM));
    const float4* __restrict__ ur = (const float4*)(u + (size_t)gw * (TSTEPS * DDIM));

    float* __restrict__ spk = out;
    float* __restrict__ mem = out + (size_t)TSTEPS * CW;

    // two row-pairs in flight: P = rows (t, t+1), Q = rows (t+2, t+3)
    float4 xp0 = z, up0 = z, xp1 = z, up1 = z;
    float4 xq0 = z, uq0 = z, xq1 = z, uq1 = z;
    if (act) {
        xp0 = xr[0 * (DDIM / 4) + lane];  up0 = ur[0 * (DDIM / 4) + lane];
        xp1 = xr[1 * (DDIM / 4) + lane];  up1 = ur[1 * (DDIM / 4) + lane];
        xq0 = xr[2 * (DDIM / 4) + lane];  uq0 = ur[2 * (DDIM / 4) + lane];
        xq1 = xr[3 * (DDIM / 4) + lane];  uq1 = ur[3 * (DDIM / 4) + lane];
    }

    float m = 0.f;   // this lane's channel membrane
    float r = 0.f;   // reset carried from previous spike

    for (int t = 0; t < TSTEPS; t += 4) {
        // ---------------- stage 1: rows t, t+1 (pair P) ----------------
        {
            // refill loads first: issue before any dependent compute
            float4 nxp0 = z, nup0 = z, nxp1 = z, nup1 = z;
            if (act && (t + 4 < TSTEPS)) {
                const int base = (t + 4) * (DDIM / 4) + lane;
                nxp0 = xr[base];              nup0 = ur[base];
                nxp1 = xr[base + (DDIM / 4)]; nup1 = ur[base + (DDIM / 4)];
            }

            const int ma = (up0.x < xp0.x) | ((up0.y < xp0.y) << 1)
                         | ((up0.z < xp0.z) << 2) | ((up0.w < xp0.w) << 3);
            const int mb = (up1.x < xp1.x) | ((up1.y < xp1.y) << 1)
                         | ((up1.z < xp1.z) << 2) | ((up1.w < xp1.w) << 3);

            const int4 la = lut[(ma << 5) | lane];
            const int4 lb = lut[(mb << 5) | lane];
            const int sa0 = __reduce_add_sync(0xffffffffu, la.x);
            const int sb0 = __reduce_add_sync(0xffffffffu, lb.x);
            const int sa1 = __reduce_add_sync(0xffffffffu, la.y);
            const int sb1 = __reduce_add_sync(0xffffffffu, lb.y);
            const int sa2 = __reduce_add_sync(0xffffffffu, la.z);
            const int sb2 = __reduce_add_sync(0xffffffffu, lb.z);

            const int ia = (lane == 0) ? sa0 : ((lane == 1) ? sa1 : sa2);
            const int ib = (lane == 0) ? sb0 : ((lane == 1) ? sb1 : sb2);
            const float pa = (float)ia * INV_FPSCALE;
            const float pb = (float)ib * INV_FPSCALE;

            m = beta * m + (pa + bl) - r;
            float sp = (m - thr > 0.f) ? 1.f : 0.f;
            r = sp * thr;
            if (lane < OOUT) {
                const size_t o = (size_t)t * CW + (size_t)gw * OOUT + lane;
                __stcs(spk + o, sp);
                __stcs(mem + o, m);
            }
            m = beta * m + (pb + bl) - r;
            sp = (m - thr > 0.f) ? 1.f : 0.f;
            r = sp * thr;
            if (lane < OOUT) {
                const size_t o = (size_t)(t + 1) * CW + (size_t)gw * OOUT + lane;
                __stcs(spk + o, sp);
                __stcs(mem + o, m);
            }

            xp0 = nxp0; up0 = nup0; xp1 = nxp1; up1 = nup1;
        }
        // ---------------- stage 2: rows t+2, t+3 (pair Q) ----------------
        {
            float4 nxq0 = z, nuq0 = z, nxq1 = z, nuq1 = z;
            if (act && (t + 6 < TSTEPS)) {
                const int base = (t + 6) * (DDIM / 4) + lane;
                nxq0 = xr[base];              nuq0 = ur[base];
                nxq1 = xr[base + (DDIM / 4)]; nuq1 = ur[base + (DDIM / 4)];
            }

            const int ma = (uq0.x < xq0.x) | ((uq0.y < xq0.y) << 1)
                         | ((uq0.z < xq0.z) << 2) | ((uq0.w < xq0.w) << 3);
            const int mb = (uq1.x < xq1.x) | ((uq1.y < xq1.y) << 1)
                         | ((uq1.z < xq1.z) << 2) | ((uq1.w < xq1.w) << 3);

            const int4 la = lut[(ma << 5) | lane];
            const int4 lb = lut[(mb << 5) | lane];
            const int sa0 = __reduce_add_sync(0xffffffffu, la.x);
            const int sb0 = __reduce_add_sync(0xffffffffu, lb.x);
            const int sa1 = __reduce_add_sync(0xffffffffu, la.y);
            const int sb1 = __reduce_add_sync(0xffffffffu, lb.y);
            const int sa2 = __reduce_add_sync(0xffffffffu, la.z);
            const int sb2 = __reduce_add_sync(0xffffffffu, lb.z);

            const int ia = (lane == 0) ? sa0 : ((lane == 1) ? sa1 : sa2);
            const int ib = (lane == 0) ? sb0 : ((lane == 1) ? sb1 : sb2);
            const float pa = (float)ia * INV_FPSCALE;
            const float pb = (float)ib * INV_FPSCALE;

            m = beta * m + (pa + bl) - r;
            float sp = (m - thr > 0.f) ? 1.f : 0.f;
            r = sp * thr;
            if (lane < OOUT) {
                const size_t o = (size_t)(t + 2) * CW + (size_t)gw * OOUT + lane;
                __stcs(spk + o, sp);
                __stcs(mem + o, m);
            }
            m = beta * m + (pb + bl) - r;
            sp = (m - thr > 0.f) ? 1.f : 0.f;
            r = sp * thr;
            if (lane < OOUT) {
                const size_t o = (size_t)(t + 3) * CW + (size_t)gw * OOUT + lane;
                __stcs(spk + o, sp);
                __stcs(mem + o, m);
            }

            xq0 = nxq0; uq0 = nuq0; xq1 = nxq1; uq1 = nuq1;
        }
    }
}

extern "C" void kernel_launch(void* const* d_in, const int* in_sizes, int n_in,
                              void* d_out, int out_size)
{
    const float* x    = (const float*)d_in[0];
    const float* u    = (const float*)d_in[1];
    const float* W    = (const float*)d_in[2];
    const float* bias = (const float*)d_in[3];
    const float* beta = (const float*)d_in[4];
    const float* thr  = (const float*)d_in[5];
    float* out = (float*)d_out;

    leaky_fused<<<BATCH / 4, 128>>>(x, u, W, bias, beta, thr, out);
}